// round 2
// baseline (speedup 1.0000x reference)
#include <cuda_runtime.h>
#include <cuda_bf16.h>

#define BATCH 64
#define DIN   1024
#define DOUT  1024

#define KT 64     // k per block
#define BT 8      // batches per block
#define JT 128    // j tile

__device__ unsigned long long g_present[BATCH];

// One block per batch: build presence bitmask of hidden_rank values (0..32).
__global__ void presence_kernel(const int* __restrict__ hidden_rank) {
    int b = blockIdx.x;
    const int* row = hidden_rank + b * DIN;
    unsigned long long m = 0ull;
    for (int t = threadIdx.x; t < DIN; t += blockDim.x)
        m |= 1ull << (row[t] & 63);
    #pragma unroll
    for (int o = 16; o; o >>= 1)
        m |= __shfl_xor_sync(0xffffffffu, m, o);
    __shared__ unsigned long long sm[8];
    int w = threadIdx.x >> 5;
    if ((threadIdx.x & 31) == 0) sm[w] = m;
    __syncthreads();
    if (threadIdx.x == 0) {
        unsigned long long r = 0ull;
        #pragma unroll
        for (int i = 0; i < 8; i++) r |= sm[i];
        g_present[b] = r;
    }
}

// Main: per block, tile of KT outputs x BT batches. Each thread: 2k x 2b register tile.
__global__ void __launch_bounds__(128, 1) masked_linear_kernel(
    const float* __restrict__ x,
    const int*   __restrict__ r_low,
    const int*   __restrict__ r_high,
    const float* __restrict__ dir,
    const float* __restrict__ cscale_b,
    const float* __restrict__ cbias_b,
    float*       __restrict__ out)
{
    __shared__ float  dir_s[KT][JT + 2];     // k-major, padded rows
    __shared__ float2 xel_s[BT][JT + 1];     // (x, el_as_float), padded

    const int tid   = threadIdx.x;           // 128 threads
    const int by    = tid & 3;                // 0..3  -> batch pair
    const int kx    = tid >> 2;               // 0..31 -> k pair
    const int kbase = blockIdx.x * KT;
    const int bbase = blockIdx.y * BT;

    const int k0  = kbase + 2 * kx;
    const int b0l = 2 * by;
    const int b1l = 2 * by + 1;

    const unsigned long long p0 = g_present[bbase + b0l];
    const unsigned long long p1 = g_present[bbase + b1l];
    const int rh0 = r_high[k0]     & 63;
    const int rh1 = r_high[k0 + 1] & 63;

    const bool om00 = (p0 >> rh0) & 1ull;
    const bool om01 = (p0 >> rh1) & 1ull;
    const bool om10 = (p1 >> rh0) & 1ull;
    const bool om11 = (p1 >> rh1) & 1ull;

    // eh = r_high if output active else 0 (el >= 1 always, so eh=0 kills all terms)
    const float eh00 = om00 ? (float)rh0 : 0.0f;
    const float eh01 = om01 ? (float)rh1 : 0.0f;
    const float eh10 = om10 ? (float)rh0 : 0.0f;
    const float eh11 = om11 ? (float)rh1 : 0.0f;

    float acc00 = 0.f, acc01 = 0.f, acc10 = 0.f, acc11 = 0.f;

    for (int j0 = 0; j0 < DIN; j0 += JT) {
        __syncthreads();

        // Load direction tile [KT x JT], scalar coalesced (no alignment assumption).
        #pragma unroll
        for (int i = tid; i < KT * JT; i += 128) {
            int kk = i >> 7;         // 0..63
            int jj = i & 127;        // 0..127
            dir_s[kk][jj] = dir[(kbase + kk) * DIN + j0 + jj];
        }

        // Load x + compute el' for BT batches of this j-tile.
        #pragma unroll
        for (int i = tid; i < BT * JT; i += 128) {
            int bb = i >> 7;         // 0..7
            int jj = i & 127;
            int j  = j0 + jj;
            int rl = r_low[j] & 63;
            unsigned long long pb = g_present[bbase + bb];
            float elf = (rl != 0 && ((pb >> rl) & 1ull)) ? (float)rl : 1e30f;
            xel_s[bb][jj] = make_float2(x[(bbase + bb) * DIN + j], elf);
        }
        __syncthreads();

        #pragma unroll 32
        for (int jj = 0; jj < JT; jj++) {
            float  d0 = dir_s[2 * kx][jj];
            float  d1 = dir_s[2 * kx + 1][jj];
            float2 e0 = xel_s[b0l][jj];
            float2 e1 = xel_s[b1l][jj];
            if (e0.y <= eh00) acc00 += d0 * e0.x;
            if (e0.y <= eh01) acc01 += d1 * e0.x;
            if (e1.y <= eh10) acc10 += d0 * e1.x;
            if (e1.y <= eh11) acc11 += d1 * e1.x;
        }
    }

    // Epilogue: out = om * (scale * y + bias); scale/bias are the Linear biases
    // (zeros @ W^T contributes 0 exactly).
    const float s0  = cscale_b[k0];
    const float s1  = cscale_b[k0 + 1];
    const float bi0 = cbias_b[k0];
    const float bi1 = cbias_b[k0 + 1];

    out[(bbase + b0l) * DOUT + k0]     = om00 ? (s0 * acc00 + bi0) : 0.0f;
    out[(bbase + b0l) * DOUT + k0 + 1] = om01 ? (s1 * acc01 + bi1) : 0.0f;
    out[(bbase + b1l) * DOUT + k0]     = om10 ? (s0 * acc10 + bi0) : 0.0f;
    out[(bbase + b1l) * DOUT + k0 + 1] = om11 ? (s1 * acc11 + bi1) : 0.0f;
}

extern "C" void kernel_launch(void* const* d_in, const int* in_sizes, int n_in,
                              void* d_out, int out_size) {
    // metadata order: x, mask, pre_mask, hidden_rank, r_low, r_high, direction,
    //                 cscale_w, cscale_b, cbias_w, cbias_b
    const float* x           = (const float*)d_in[0];
    const int*   hidden_rank = (const int*)  d_in[3];
    const int*   r_low       = (const int*)  d_in[4];
    const int*   r_high      = (const int*)  d_in[5];
    const float* dir         = (const float*)d_in[6];
    const float* cscale_b    = (const float*)d_in[8];
    const float* cbias_b     = (const float*)d_in[10];
    float* out = (float*)d_out;

    presence_kernel<<<BATCH, 256>>>(hidden_rank);
    masked_linear_kernel<<<dim3(DOUT / KT, BATCH / BT), 128>>>(
        x, r_low, r_high, dir, cscale_b, cbias_b, out);
}

// round 3
// speedup vs baseline: 1.0278x; 1.0278x over previous
#include <cuda_runtime.h>
#include <cuda_bf16.h>

#define BATCH 64
#define DIN   1024
#define DOUT  1024

#define KT 64     // k per block
#define BT 8      // batches per block
#define JT 128    // j tile

__device__ unsigned long long g_present[BATCH];

// One block per batch: build presence bitmask of hidden_rank values (0..32).
__global__ void presence_kernel(const int* __restrict__ hidden_rank) {
    int b = blockIdx.x;
    const int* row = hidden_rank + b * DIN;
    unsigned long long m = 0ull;
    for (int t = threadIdx.x; t < DIN; t += blockDim.x)
        m |= 1ull << (row[t] & 63);
    #pragma unroll
    for (int o = 16; o; o >>= 1)
        m |= __shfl_xor_sync(0xffffffffu, m, o);
    __shared__ unsigned long long sm[8];
    int w = threadIdx.x >> 5;
    if ((threadIdx.x & 31) == 0) sm[w] = m;
    __syncthreads();
    if (threadIdx.x == 0) {
        unsigned long long r = 0ull;
        #pragma unroll
        for (int i = 0; i < 8; i++) r |= sm[i];
        g_present[b] = r;
    }
}

// Main: per block, tile of KT outputs x BT batches. Each thread: 2k x 2b register tile.
__global__ void __launch_bounds__(128, 1) masked_linear_kernel(
    const float* __restrict__ x,
    const int*   __restrict__ r_low,
    const int*   __restrict__ r_high,
    const float* __restrict__ dir,
    const float* __restrict__ cscale_b,
    const float* __restrict__ cbias_b,
    float*       __restrict__ out)
{
    __shared__ float  dir_s[KT][JT + 2];     // k-major, padded rows
    __shared__ float2 xel_s[BT][JT + 1];     // (x, el_as_float), padded

    const int tid   = threadIdx.x;           // 128 threads
    const int by    = tid & 3;                // 0..3  -> batch pair
    const int kx    = tid >> 2;               // 0..31 -> k pair
    const int kbase = blockIdx.x * KT;
    const int bbase = blockIdx.y * BT;

    const int k0  = kbase + 2 * kx;
    const int b0l = 2 * by;
    const int b1l = 2 * by + 1;

    const unsigned long long p0 = g_present[bbase + b0l];
    const unsigned long long p1 = g_present[bbase + b1l];
    const int rh0 = r_high[k0]     & 63;
    const int rh1 = r_high[k0 + 1] & 63;

    const bool om00 = (p0 >> rh0) & 1ull;
    const bool om01 = (p0 >> rh1) & 1ull;
    const bool om10 = (p1 >> rh0) & 1ull;
    const bool om11 = (p1 >> rh1) & 1ull;

    // eh = r_high if output active else 0 (el >= 1 always, so eh=0 kills all terms)
    const float eh00 = om00 ? (float)rh0 : 0.0f;
    const float eh01 = om01 ? (float)rh1 : 0.0f;
    const float eh10 = om10 ? (float)rh0 : 0.0f;
    const float eh11 = om11 ? (float)rh1 : 0.0f;

    float acc00 = 0.f, acc01 = 0.f, acc10 = 0.f, acc11 = 0.f;

    for (int j0 = 0; j0 < DIN; j0 += JT) {
        __syncthreads();

        // Load direction tile [KT x JT], scalar coalesced (no alignment assumption).
        #pragma unroll
        for (int i = tid; i < KT * JT; i += 128) {
            int kk = i >> 7;         // 0..63
            int jj = i & 127;        // 0..127
            dir_s[kk][jj] = dir[(kbase + kk) * DIN + j0 + jj];
        }

        // Load x + compute el' for BT batches of this j-tile.
        #pragma unroll
        for (int i = tid; i < BT * JT; i += 128) {
            int bb = i >> 7;         // 0..7
            int jj = i & 127;
            int j  = j0 + jj;
            int rl = r_low[j] & 63;
            unsigned long long pb = g_present[bbase + bb];
            float elf = (rl != 0 && ((pb >> rl) & 1ull)) ? (float)rl : 1e30f;
            xel_s[bb][jj] = make_float2(x[(bbase + bb) * DIN + j], elf);
        }
        __syncthreads();

        #pragma unroll 32
        for (int jj = 0; jj < JT; jj++) {
            float  d0 = dir_s[2 * kx][jj];
            float  d1 = dir_s[2 * kx + 1][jj];
            float2 e0 = xel_s[b0l][jj];
            float2 e1 = xel_s[b1l][jj];
            if (e0.y <= eh00) acc00 += d0 * e0.x;
            if (e0.y <= eh01) acc01 += d1 * e0.x;
            if (e1.y <= eh10) acc10 += d0 * e1.x;
            if (e1.y <= eh11) acc11 += d1 * e1.x;
        }
    }

    // Epilogue: out = om * (scale * y + bias); scale/bias are the Linear biases
    // (zeros @ W^T contributes 0 exactly).
    const float s0  = cscale_b[k0];
    const float s1  = cscale_b[k0 + 1];
    const float bi0 = cbias_b[k0];
    const float bi1 = cbias_b[k0 + 1];

    out[(bbase + b0l) * DOUT + k0]     = om00 ? (s0 * acc00 + bi0) : 0.0f;
    out[(bbase + b0l) * DOUT + k0 + 1] = om01 ? (s1 * acc01 + bi1) : 0.0f;
    out[(bbase + b1l) * DOUT + k0]     = om10 ? (s0 * acc10 + bi0) : 0.0f;
    out[(bbase + b1l) * DOUT + k0 + 1] = om11 ? (s1 * acc11 + bi1) : 0.0f;
}

extern "C" void kernel_launch(void* const* d_in, const int* in_sizes, int n_in,
                              void* d_out, int out_size) {
    // metadata order: x, mask, pre_mask, hidden_rank, r_low, r_high, direction,
    //                 cscale_w, cscale_b, cbias_w, cbias_b
    const float* x           = (const float*)d_in[0];
    const int*   hidden_rank = (const int*)  d_in[3];
    const int*   r_low       = (const int*)  d_in[4];
    const int*   r_high      = (const int*)  d_in[5];
    const float* dir         = (const float*)d_in[6];
    const float* cscale_b    = (const float*)d_in[8];
    const float* cbias_b     = (const float*)d_in[10];
    float* out = (float*)d_out;

    presence_kernel<<<BATCH, 256>>>(hidden_rank);
    masked_linear_kernel<<<dim3(DOUT / KT, BATCH / BT), 128>>>(
        x, r_low, r_high, dir, cscale_b, cbias_b, out);
}